// round 7
// baseline (speedup 1.0000x reference)
#include <cuda_runtime.h>
#include <cuda_fp16.h>

#define NMAX 100000
#define EMAX 1600000
#define CMAX 128

// Scratch (__device__ globals: allocation-free rule)
__device__ __half d_G1[(size_t)NMAX * CMAX];   // layer-1 messages
__device__ __half d_G2[(size_t)NMAX * CMAX];   // layer-2 messages
__device__ __half d_G3[(size_t)NMAX * 64];     // layer-3 messages
__device__ float  d_dinv[NMAX];
__device__ int    d_cnt[NMAX];
__device__ int    d_cur[NMAX];
__device__ int    d_off[NMAX + 1];
__device__ int    d_csr[EMAX];
__device__ int    d_blk[128];
__device__ int    d_blk2[128];
__device__ unsigned d_gmin[64];

#define FMA2(d, a, b, c) \
    asm("fma.rn.f32x2 %0, %1, %2, %3;" : "=l"(d) : "l"(a), "l"(b), "l"(c))
#define PACK2(d, x) \
    asm("mov.b64 %0, {%1, %1};" : "=l"(d) : "f"(x))
#define UNPACK2(lo, hi, v) \
    asm("mov.b64 {%0, %1}, %2;" : "=f"(lo), "=f"(hi) : "l"(v))

__device__ __forceinline__ unsigned enc_f(float f) {
    unsigned u = __float_as_uint(f);
    return (u & 0x80000000u) ? ~u : (u | 0x80000000u);
}
__device__ __forceinline__ float dec_f(unsigned e) {
    unsigned u = (e & 0x80000000u) ? (e ^ 0x80000000u) : ~e;
    return __uint_as_float(u);
}

// ================= degree histogram =================
__global__ void k_hist(const int* __restrict__ dst, int E) {
    int i = blockIdx.x * blockDim.x + threadIdx.x;
    if (i < E) atomicAdd(&d_cnt[dst[i]], 1);
}

// ================= CSR scans =================
__global__ void k_scan1(int N) {
    __shared__ int sh[256];
    int t = threadIdx.x;
    int base = blockIdx.x * 1024 + t * 4;
    int c0 = 0, c1 = 0, c2 = 0, c3 = 0;
    if (base + 3 < N) {
        int4 v = *(const int4*)&d_cnt[base];
        c0 = v.x; c1 = v.y; c2 = v.z; c3 = v.w;
    } else {
        if (base + 0 < N) c0 = d_cnt[base + 0];
        if (base + 1 < N) c1 = d_cnt[base + 1];
        if (base + 2 < N) c2 = d_cnt[base + 2];
        if (base + 3 < N) c3 = d_cnt[base + 3];
    }
    int s = c0 + c1 + c2 + c3;
    sh[t] = s;
    __syncthreads();
    for (int d = 1; d < 256; d <<= 1) {
        int v = (t >= d) ? sh[t - d] : 0;
        __syncthreads();
        sh[t] += v;
        __syncthreads();
    }
    int excl = sh[t] - s;
    if (base + 0 < N) d_off[base + 0] = excl;
    if (base + 1 < N) d_off[base + 1] = excl + c0;
    if (base + 2 < N) d_off[base + 2] = excl + c0 + c1;
    if (base + 3 < N) d_off[base + 3] = excl + c0 + c1 + c2;
    if (t == 255) d_blk[blockIdx.x] = sh[255];
}

__global__ void k_scan2(int nblk) {
    __shared__ int sh[128];
    int t = threadIdx.x;
    int v = (t < nblk) ? d_blk[t] : 0;
    sh[t] = v;
    __syncthreads();
    for (int d = 1; d < 128; d <<= 1) {
        int u = (t >= d) ? sh[t - d] : 0;
        __syncthreads();
        sh[t] += u;
        __syncthreads();
    }
    d_blk2[t] = sh[t] - v;
}

// Also: computes dinv, zeroes d_cnt/d_cur for graph replay, inits gmin.
__global__ void k_scan3(int N, int E) {
    int i = blockIdx.x * blockDim.x + threadIdx.x;
    if (i < N) {
        d_off[i] += d_blk2[i >> 10];
        d_dinv[i] = rsqrtf((float)d_cnt[i] + 1.0f);  // +1 self-loop
        d_cnt[i] = 0;                                 // self-clean for replay
        d_cur[i] = 0;
    }
    if (i == 0) d_off[N] = E;
    if (blockIdx.x == 0 && threadIdx.x < 64) d_gmin[threadIdx.x] = 0xFFFFFFFFu;
}

// ================= layer-1 GEMM: G1[row] = half(dinv[row]*(x[row]@W1)) ==========
// 128 threads, 8x8 thread tile, f32x2. Blocks with bid < fillBlocks do CSR fill
// (low bids start first -> overlap with GEMM waves; scan3 already ran).
template <int COLS, int TROWS>
__global__ void __launch_bounds__(128)
k_gemm1(const float* __restrict__ A, const float* __restrict__ W,
        __half* __restrict__ g, int N,
        const int* __restrict__ src, const int* __restrict__ dstp, int E, int fillBlocks)
{
    if ((int)blockIdx.x < fillBlocks) {
        for (int i = blockIdx.x * 128 + threadIdx.x; i < E; i += fillBlocks * 128) {
            int d = dstp[i];
            int p = atomicAdd(&d_cur[d], 1);
            d_csr[d_off[d] + p] = src[i];
        }
        return;
    }
    extern __shared__ float sm[];
    constexpr int RS = TROWS + 4;
    float* Xs = sm;               // [128][RS] transposed (k-major, row-fast)
    float* Ws = sm + 128 * RS;    // [128][COLS]
    constexpr int CG = COLS / 8;
    const int tid = threadIdx.x;
    const int cg = tid % CG;
    const int rg = tid / CG;
    const int base = (blockIdx.x - fillBlocks) * TROWS;

    for (int i = tid; i < 128 * COLS / 4; i += 128)
        ((float4*)Ws)[i] = __ldg((const float4*)W + i);

    for (int i = tid; i < TROWS * 32; i += 128) {
        int r = i % TROWS;
        int k4 = i / TROWS;
        int row = base + r;
        float4 v = make_float4(0.f, 0.f, 0.f, 0.f);
        if (row < N) v = __ldg((const float4*)(A + (size_t)row * 128) + k4);
        int k = k4 * 4;
        Xs[(k + 0) * RS + r] = v.x;
        Xs[(k + 1) * RS + r] = v.y;
        Xs[(k + 2) * RS + r] = v.z;
        Xs[(k + 3) * RS + r] = v.w;
    }
    __syncthreads();

    unsigned long long acc[8][4];
#pragma unroll
    for (int r = 0; r < 8; r++)
#pragma unroll
        for (int c = 0; c < 4; c++) acc[r][c] = 0ull;

#pragma unroll 4
    for (int k = 0; k < 128; k++) {
        float4 xa = *(const float4*)&Xs[k * RS + rg * 8];
        float4 xb = *(const float4*)&Xs[k * RS + rg * 8 + 4];
        float xr[8] = {xa.x, xa.y, xa.z, xa.w, xb.x, xb.y, xb.z, xb.w};
        unsigned long long x2[8];
#pragma unroll
        for (int r = 0; r < 8; r++) PACK2(x2[r], xr[r]);
        ulonglong2 wA = *(const ulonglong2*)&Ws[k * COLS + cg * 8];
        ulonglong2 wB = *(const ulonglong2*)&Ws[k * COLS + cg * 8 + 4];
        unsigned long long w2[4] = {wA.x, wA.y, wB.x, wB.y};
#pragma unroll
        for (int r = 0; r < 8; r++)
#pragma unroll
            for (int c = 0; c < 4; c++) FMA2(acc[r][c], x2[r], w2[c], acc[r][c]);
    }

#pragma unroll
    for (int r = 0; r < 8; r++) {
        int row = base + rg * 8 + r;
        if (row < N) {
            float dv = d_dinv[row];
            __half2 h[4];
#pragma unroll
            for (int c = 0; c < 4; c++) {
                float lo, hi;
                UNPACK2(lo, hi, acc[r][c]);
                h[c] = __floats2half2_rn(lo * dv, hi * dv);
            }
            *(uint4*)(g + (size_t)row * COLS + cg * 8) = *(uint4*)h;
        }
    }
}

// ================= fused aggregate + GEMM ==========================
// Phase A: 8 warps aggregate TROWS nodes' neighborhoods from g_in (128 half cols),
//          apply relu(dinv*sum + bias), write fp32 rows into smem (row-major, S=129).
// Phase B: GEMM from smem with W (128 x COLS), f32x2, thread tile 4x8.
// Epilogue: g_out[row] = half(dinv[row] * result)   (messages for next layer)
template <int COLS, int TROWS>
__global__ void __launch_bounds__(256)
k_aggGemm(const __half* __restrict__ g_in, const float* __restrict__ W,
          const float* __restrict__ bias, __half* __restrict__ g_out, int N)
{
    extern __shared__ float sm[];
    constexpr int S = 129;                 // odd-ish stride (mult of 1) for LDS spread
    float* Xr = sm;                        // [TROWS][S] row-major activations
    float* Ws = sm + TROWS * S;            // [128][COLS]
    const int tid = threadIdx.x;
    const int base = blockIdx.x * TROWS;

    for (int i = tid; i < 128 * COLS / 4; i += 256)
        ((float4*)Ws)[i] = __ldg((const float4*)W + i);

    // ---- Phase A: aggregate ----
    {
        int wid = tid >> 5;
        int lane = tid & 31;
        const uint2* gp = (const uint2*)g_in;
#pragma unroll 1
        for (int i = 0; i < TROWS / 8; i++) {
            int r = i * 8 + wid;
            int row = base + r;
            float a0 = 0.f, a1 = 0.f, a2 = 0.f, a3 = 0.f;
            if (row < N) {
                uint2 v = __ldg(&gp[(size_t)row * 32 + lane]);   // self-loop
                float2 f0 = __half22float2(*(__half2*)&v.x);
                float2 f1 = __half22float2(*(__half2*)&v.y);
                a0 += f0.x; a1 += f0.y; a2 += f1.x; a3 += f1.y;
                int s = d_off[row], e = d_off[row + 1];
                int j = s;
                for (; j + 4 <= e; j += 4) {
                    int n0 = d_csr[j], n1 = d_csr[j + 1], n2 = d_csr[j + 2], n3 = d_csr[j + 3];
                    uint2 v0 = __ldg(&gp[(size_t)n0 * 32 + lane]);
                    uint2 v1 = __ldg(&gp[(size_t)n1 * 32 + lane]);
                    uint2 v2 = __ldg(&gp[(size_t)n2 * 32 + lane]);
                    uint2 v3 = __ldg(&gp[(size_t)n3 * 32 + lane]);
                    float2 f;
                    f = __half22float2(*(__half2*)&v0.x); a0 += f.x; a1 += f.y;
                    f = __half22float2(*(__half2*)&v0.y); a2 += f.x; a3 += f.y;
                    f = __half22float2(*(__half2*)&v1.x); a0 += f.x; a1 += f.y;
                    f = __half22float2(*(__half2*)&v1.y); a2 += f.x; a3 += f.y;
                    f = __half22float2(*(__half2*)&v2.x); a0 += f.x; a1 += f.y;
                    f = __half22float2(*(__half2*)&v2.y); a2 += f.x; a3 += f.y;
                    f = __half22float2(*(__half2*)&v3.x); a0 += f.x; a1 += f.y;
                    f = __half22float2(*(__half2*)&v3.y); a2 += f.x; a3 += f.y;
                }
                for (; j < e; j++) {
                    uint2 vv = __ldg(&gp[(size_t)d_csr[j] * 32 + lane]);
                    float2 g0 = __half22float2(*(__half2*)&vv.x);
                    float2 g1 = __half22float2(*(__half2*)&vv.y);
                    a0 += g0.x; a1 += g0.y; a2 += g1.x; a3 += g1.y;
                }
                float dv = d_dinv[row];
                float4 b = __ldg((const float4*)bias + lane);
                a0 = fmaxf(fmaf(a0, dv, b.x), 0.f);
                a1 = fmaxf(fmaf(a1, dv, b.y), 0.f);
                a2 = fmaxf(fmaf(a2, dv, b.z), 0.f);
                a3 = fmaxf(fmaf(a3, dv, b.w), 0.f);
            }
            float* xp = Xr + r * S + lane * 4;
            xp[0] = a0; xp[1] = a1; xp[2] = a2; xp[3] = a3;
        }
    }
    __syncthreads();

    // ---- Phase B: GEMM (thread tile 4 rows x 8 cols = 4x4 f32x2) ----
    constexpr int CG = COLS / 8;
    const int cg = tid % CG;
    const int rg = tid / CG;               // 256/CG row groups x 4 rows = TROWS

    unsigned long long acc[4][4];
#pragma unroll
    for (int r = 0; r < 4; r++)
#pragma unroll
        for (int c = 0; c < 4; c++) acc[r][c] = 0ull;

    const float* x0 = Xr + (rg * 4 + 0) * S;
    const float* x1 = Xr + (rg * 4 + 1) * S;
    const float* x2p = Xr + (rg * 4 + 2) * S;
    const float* x3p = Xr + (rg * 4 + 3) * S;

#pragma unroll 4
    for (int k = 0; k < 128; k++) {
        unsigned long long xp[4];
        PACK2(xp[0], x0[k]);
        PACK2(xp[1], x1[k]);
        PACK2(xp[2], x2p[k]);
        PACK2(xp[3], x3p[k]);
        ulonglong2 wA = *(const ulonglong2*)&Ws[k * COLS + cg * 8];
        ulonglong2 wB = *(const ulonglong2*)&Ws[k * COLS + cg * 8 + 4];
        unsigned long long w2[4] = {wA.x, wA.y, wB.x, wB.y};
#pragma unroll
        for (int r = 0; r < 4; r++)
#pragma unroll
            for (int c = 0; c < 4; c++) FMA2(acc[r][c], xp[r], w2[c], acc[r][c]);
    }

#pragma unroll
    for (int r = 0; r < 4; r++) {
        int row = base + rg * 4 + r;
        if (row < N) {
            float dv = d_dinv[row];
            __half2 h[4];
#pragma unroll
            for (int c = 0; c < 4; c++) {
                float lo, hi;
                UNPACK2(lo, hi, acc[r][c]);
                h[c] = __floats2half2_rn(lo * dv, hi * dv);
            }
            *(uint4*)(g_out + (size_t)row * COLS + cg * 8) = *(uint4*)h;
        }
    }
}

// ================= layer-3 aggregate + fused min-pool =================
// G3 rows: 64 halves = 32 half2; lane covers cols {2*lane, 2*lane+1}.
__global__ void k_agg64min(const __half* __restrict__ g, int N)
{
    __shared__ unsigned sMin[64];
    int tid = threadIdx.x;
    if (tid < 64) sMin[tid] = 0xFFFFFFFFu;
    __syncthreads();

    int node = (blockIdx.x * blockDim.x + tid) >> 5;
    int lane = tid & 31;
    if (node < N) {
        const unsigned* gp = (const unsigned*)g;
        float a0 = 0.f, a1 = 0.f;
        {
            unsigned v = __ldg(&gp[(size_t)node * 32 + lane]);
            float2 f = __half22float2(*(__half2*)&v);
            a0 += f.x; a1 += f.y;
        }
        int s = d_off[node], e = d_off[node + 1];
        int j = s;
        for (; j + 4 <= e; j += 4) {
            int n0 = d_csr[j], n1 = d_csr[j + 1], n2 = d_csr[j + 2], n3 = d_csr[j + 3];
            unsigned v0 = __ldg(&gp[(size_t)n0 * 32 + lane]);
            unsigned v1 = __ldg(&gp[(size_t)n1 * 32 + lane]);
            unsigned v2 = __ldg(&gp[(size_t)n2 * 32 + lane]);
            unsigned v3 = __ldg(&gp[(size_t)n3 * 32 + lane]);
            float2 f;
            f = __half22float2(*(__half2*)&v0); a0 += f.x; a1 += f.y;
            f = __half22float2(*(__half2*)&v1); a0 += f.x; a1 += f.y;
            f = __half22float2(*(__half2*)&v2); a0 += f.x; a1 += f.y;
            f = __half22float2(*(__half2*)&v3); a0 += f.x; a1 += f.y;
        }
        for (; j < e; j++) {
            unsigned v = __ldg(&gp[(size_t)d_csr[j] * 32 + lane]);
            float2 f = __half22float2(*(__half2*)&v);
            a0 += f.x; a1 += f.y;
        }
        float dv = d_dinv[node];
        atomicMin(&sMin[2 * lane + 0], enc_f(a0 * dv));
        atomicMin(&sMin[2 * lane + 1], enc_f(a1 * dv));
    }
    __syncthreads();
    if (tid < 64) atomicMin(&d_gmin[tid], sMin[tid]);
}

__global__ void k_final(const float* __restrict__ b3, float* __restrict__ out) {
    int c = threadIdx.x;
    out[c] = dec_f(d_gmin[c]) + b3[c];
}

extern "C" void kernel_launch(void* const* d_in, const int* in_sizes, int n_in,
                              void* d_out, int out_size)
{
    const float* x  = (const float*)d_in[0];
    const int*   ei = (const int*)d_in[1];
    const float* W1 = (const float*)d_in[2];
    const float* b1 = (const float*)d_in[3];
    const float* W2 = (const float*)d_in[4];
    const float* b2 = (const float*)d_in[5];
    const float* W3 = (const float*)d_in[6];
    const float* b3 = (const float*)d_in[7];
    float* out = (float*)d_out;

    int N = in_sizes[0] / 128;
    int E = in_sizes[1] / 2;
    const int* src = ei;
    const int* dst = ei + E;

    __half *G1, *G2, *G3;
    cudaGetSymbolAddress((void**)&G1, d_G1);
    cudaGetSymbolAddress((void**)&G2, d_G2);
    cudaGetSymbolAddress((void**)&G3, d_G3);

    const int smem1  = (128 * (64 + 4) + 128 * 128) * 4;        // k_gemm1<128,64>
    const int smemA2 = (64 * 129 + 128 * 128) * 4;              // k_aggGemm<128,64>
    const int smemA3 = (128 * 129 + 128 * 64) * 4;              // k_aggGemm<64,128>
    cudaFuncSetAttribute(k_gemm1<128, 64>,   cudaFuncAttributeMaxDynamicSharedMemorySize, smem1);
    cudaFuncSetAttribute(k_aggGemm<128, 64>, cudaFuncAttributeMaxDynamicSharedMemorySize, smemA2);
    cudaFuncSetAttribute(k_aggGemm<64, 128>, cudaFuncAttributeMaxDynamicSharedMemorySize, smemA3);

    // CSR: hist + scans (dinv ready after scan3; cnt/cur self-cleaned there)
    k_hist<<<(E + 255) / 256, 256>>>(dst, E);
    int nblk = (N + 1023) / 1024;
    k_scan1<<<nblk, 256>>>(N);
    k_scan2<<<1, 128>>>(nblk);
    k_scan3<<<(N + 255) / 256, 256>>>(N, E);

    // Layer 1: GEMM (x @ W1 -> G1) with CSR fill fused at low block ids
    const int fillBlocks = 1024;
    int gb1 = (N + 63) / 64;
    k_gemm1<128, 64><<<gb1 + fillBlocks, 128, smem1>>>(x, W1, G1, N, src, dst, E, fillBlocks);

    // Layer 2: fused aggregate(G1)+relu+b1 -> GEMM W2 -> G2
    k_aggGemm<128, 64><<<(N + 63) / 64, 256, smemA2>>>(G1, W2, b1, G2, N);

    // Layer 3: fused aggregate(G2)+relu+b2 -> GEMM W3 -> G3 (64 cols)
    k_aggGemm<64, 128><<<(N + 127) / 128, 256, smemA3>>>(G2, W3, b2, G3, N);

    // Final aggregate + min-pool
    k_agg64min<<<(N * 32 + 255) / 256, 256>>>(G3, N);
    k_final<<<1, 64>>>(b3, out);
}

// round 8
// speedup vs baseline: 1.3230x; 1.3230x over previous
#include <cuda_runtime.h>
#include <cuda_fp16.h>

#define NMAX 100000
#define EMAX 1600000
#define CMAX 128

// Scratch (__device__ globals: allocation-free rule)
__device__ __half d_G[(size_t)NMAX * CMAX];       // messages (half)
__device__ float  d_B1[(size_t)NMAX * CMAX];      // layer activations (fp32)
__device__ float  d_B2[(size_t)NMAX * CMAX];
__device__ float  d_dinv[NMAX];
__device__ int    d_cnt[NMAX];
__device__ int    d_cur[NMAX];
__device__ int    d_off[NMAX + 1];
__device__ int    d_csr[EMAX];
__device__ int    d_blk[128];
__device__ int    d_blk2[128];
__device__ unsigned d_gmin[64];

#define FMA2(d, a, b, c) \
    asm("fma.rn.f32x2 %0, %1, %2, %3;" : "=l"(d) : "l"(a), "l"(b), "l"(c))
#define PACK2(d, x) \
    asm("mov.b64 %0, {%1, %1};" : "=l"(d) : "f"(x))
#define UNPACK2(lo, hi, v) \
    asm("mov.b64 {%0, %1}, %2;" : "=f"(lo), "=f"(hi) : "l"(v))

__device__ __forceinline__ unsigned enc_f(float f) {
    unsigned u = __float_as_uint(f);
    return (u & 0x80000000u) ? ~u : (u | 0x80000000u);
}
__device__ __forceinline__ float dec_f(unsigned e) {
    unsigned u = (e & 0x80000000u) ? (e ^ 0x80000000u) : ~e;
    return __uint_as_float(u);
}

// ================= degree histogram =================
__global__ void k_hist(const int* __restrict__ dst, int E) {
    int i = blockIdx.x * blockDim.x + threadIdx.x;
    if (i < E) atomicAdd(&d_cnt[dst[i]], 1);
}

// ================= CSR scans =================
__global__ void k_scan1(int N) {
    __shared__ int sh[256];
    int t = threadIdx.x;
    int base = blockIdx.x * 1024 + t * 4;
    int c0 = 0, c1 = 0, c2 = 0, c3 = 0;
    if (base + 3 < N) {
        int4 v = *(const int4*)&d_cnt[base];
        c0 = v.x; c1 = v.y; c2 = v.z; c3 = v.w;
    } else {
        if (base + 0 < N) c0 = d_cnt[base + 0];
        if (base + 1 < N) c1 = d_cnt[base + 1];
        if (base + 2 < N) c2 = d_cnt[base + 2];
        if (base + 3 < N) c3 = d_cnt[base + 3];
    }
    int s = c0 + c1 + c2 + c3;
    sh[t] = s;
    __syncthreads();
    for (int d = 1; d < 256; d <<= 1) {
        int v = (t >= d) ? sh[t - d] : 0;
        __syncthreads();
        sh[t] += v;
        __syncthreads();
    }
    int excl = sh[t] - s;
    if (base + 0 < N) d_off[base + 0] = excl;
    if (base + 1 < N) d_off[base + 1] = excl + c0;
    if (base + 2 < N) d_off[base + 2] = excl + c0 + c1;
    if (base + 3 < N) d_off[base + 3] = excl + c0 + c1 + c2;
    if (t == 255) d_blk[blockIdx.x] = sh[255];
}

__global__ void k_scan2(int nblk) {
    __shared__ int sh[128];
    int t = threadIdx.x;
    int v = (t < nblk) ? d_blk[t] : 0;
    sh[t] = v;
    __syncthreads();
    for (int d = 1; d < 128; d <<= 1) {
        int u = (t >= d) ? sh[t - d] : 0;
        __syncthreads();
        sh[t] += u;
        __syncthreads();
    }
    d_blk2[t] = sh[t] - v;
}

// Also: computes dinv, zeroes d_cnt/d_cur for graph replay, inits gmin.
__global__ void k_scan3(int N, int E) {
    int i = blockIdx.x * blockDim.x + threadIdx.x;
    if (i < N) {
        d_off[i] += d_blk2[i >> 10];
        d_dinv[i] = rsqrtf((float)d_cnt[i] + 1.0f);  // +1 self-loop
        d_cnt[i] = 0;                                 // self-clean for replay
        d_cur[i] = 0;
    }
    if (i == 0) d_off[N] = E;
    if (blockIdx.x == 0 && threadIdx.x < 64) d_gmin[threadIdx.x] = 0xFFFFFFFFu;
}

// ================= GEMM: g[row] = half(dinv[row] * (A[row] @ W)) =================
// 128 threads; each computes an 8x8 tile via fma.rn.f32x2.
// FILL: blocks with bid < fillBlocks do the CSR fill instead (low bids start
// in the first wave, overlapping the GEMM; scan3 already ran).
template <int COLS, int TROWS, bool FILL>
__global__ void __launch_bounds__(128)
k_gemm(const float* __restrict__ A, const float* __restrict__ W,
       __half* __restrict__ g, int N,
       const int* __restrict__ src, const int* __restrict__ dstp, int E, int fillBlocks)
{
    if (FILL && (int)blockIdx.x < fillBlocks) {
        for (int i = blockIdx.x * 128 + threadIdx.x; i < E; i += fillBlocks * 128) {
            int d = dstp[i];
            int p = atomicAdd(&d_cur[d], 1);
            d_csr[d_off[d] + p] = src[i];
        }
        return;
    }
    extern __shared__ float sm[];
    constexpr int RS = TROWS + 4;
    float* Xs = sm;               // [128][RS] transposed (k-major, row-fast)
    float* Ws = sm + 128 * RS;    // [128][COLS]
    constexpr int CG = COLS / 8;
    const int tid = threadIdx.x;
    const int cg = tid % CG;
    const int rg = tid / CG;
    const int base = (blockIdx.x - (FILL ? fillBlocks : 0)) * TROWS;

    for (int i = tid; i < 128 * COLS / 4; i += 128)
        ((float4*)Ws)[i] = __ldg((const float4*)W + i);

    for (int i = tid; i < TROWS * 32; i += 128) {
        int r = i % TROWS;
        int k4 = i / TROWS;
        int row = base + r;
        float4 v = make_float4(0.f, 0.f, 0.f, 0.f);
        if (row < N) v = __ldg((const float4*)(A + (size_t)row * 128) + k4);
        int k = k4 * 4;
        Xs[(k + 0) * RS + r] = v.x;
        Xs[(k + 1) * RS + r] = v.y;
        Xs[(k + 2) * RS + r] = v.z;
        Xs[(k + 3) * RS + r] = v.w;
    }
    __syncthreads();

    unsigned long long acc[8][4];
#pragma unroll
    for (int r = 0; r < 8; r++)
#pragma unroll
        for (int c = 0; c < 4; c++) acc[r][c] = 0ull;

#pragma unroll 4
    for (int k = 0; k < 128; k++) {
        float4 xa = *(const float4*)&Xs[k * RS + rg * 8];
        float4 xb = *(const float4*)&Xs[k * RS + rg * 8 + 4];
        float xr[8] = {xa.x, xa.y, xa.z, xa.w, xb.x, xb.y, xb.z, xb.w};
        unsigned long long x2[8];
#pragma unroll
        for (int r = 0; r < 8; r++) PACK2(x2[r], xr[r]);
        ulonglong2 wA = *(const ulonglong2*)&Ws[k * COLS + cg * 8];
        ulonglong2 wB = *(const ulonglong2*)&Ws[k * COLS + cg * 8 + 4];
        unsigned long long w2[4] = {wA.x, wA.y, wB.x, wB.y};
#pragma unroll
        for (int r = 0; r < 8; r++)
#pragma unroll
            for (int c = 0; c < 4; c++) FMA2(acc[r][c], x2[r], w2[c], acc[r][c]);
    }

#pragma unroll
    for (int r = 0; r < 8; r++) {
        int row = base + rg * 8 + r;
        if (row < N) {
            float dv = d_dinv[row];
            __half2 h[4];
#pragma unroll
            for (int c = 0; c < 4; c++) {
                float lo, hi;
                UNPACK2(lo, hi, acc[r][c]);
                h[c] = __floats2half2_rn(lo * dv, hi * dv);
            }
            *(uint4*)(g + (size_t)row * COLS + cg * 8) = *(uint4*)h;
        }
    }
}

// ================= CSR aggregate (half msgs, fp32 accum, 1 warp/node) ============
// Index loads for batch i+1 are issued before batch i's row data is consumed
// (software pipelining: breaks the idx->row dependent-latency chain).
__global__ void k_agg128(const __half* __restrict__ g, const float* __restrict__ bias,
                         float* __restrict__ out, int N)
{
    int node = (blockIdx.x * blockDim.x + threadIdx.x) >> 5;
    int lane = threadIdx.x & 31;
    if (node >= N) return;
    const uint2* gp = (const uint2*)g;

    float a0 = 0.f, a1 = 0.f, a2 = 0.f, a3 = 0.f;
    {
        uint2 v = __ldg(&gp[(size_t)node * 32 + lane]);  // self-loop
        float2 f0 = __half22float2(*(__half2*)&v.x);
        float2 f1 = __half22float2(*(__half2*)&v.y);
        a0 += f0.x; a1 += f0.y; a2 += f1.x; a3 += f1.y;
    }
    int s = d_off[node], e = d_off[node + 1];
    int j = s;
    int n0, n1, n2, n3;
    bool have = (j + 4 <= e);
    if (have) {
        n0 = __ldg(d_csr + j);     n1 = __ldg(d_csr + j + 1);
        n2 = __ldg(d_csr + j + 2); n3 = __ldg(d_csr + j + 3);
    }
    while (have) {
        bool nxt = (j + 8 <= e);
        int m0, m1, m2, m3;
        if (nxt) {                                   // prefetch next indices
            m0 = __ldg(d_csr + j + 4); m1 = __ldg(d_csr + j + 5);
            m2 = __ldg(d_csr + j + 6); m3 = __ldg(d_csr + j + 7);
        }
        uint2 v0 = __ldg(&gp[(size_t)n0 * 32 + lane]);
        uint2 v1 = __ldg(&gp[(size_t)n1 * 32 + lane]);
        uint2 v2 = __ldg(&gp[(size_t)n2 * 32 + lane]);
        uint2 v3 = __ldg(&gp[(size_t)n3 * 32 + lane]);
        float2 f;
        f = __half22float2(*(__half2*)&v0.x); a0 += f.x; a1 += f.y;
        f = __half22float2(*(__half2*)&v0.y); a2 += f.x; a3 += f.y;
        f = __half22float2(*(__half2*)&v1.x); a0 += f.x; a1 += f.y;
        f = __half22float2(*(__half2*)&v1.y); a2 += f.x; a3 += f.y;
        f = __half22float2(*(__half2*)&v2.x); a0 += f.x; a1 += f.y;
        f = __half22float2(*(__half2*)&v2.y); a2 += f.x; a3 += f.y;
        f = __half22float2(*(__half2*)&v3.x); a0 += f.x; a1 += f.y;
        f = __half22float2(*(__half2*)&v3.y); a2 += f.x; a3 += f.y;
        n0 = m0; n1 = m1; n2 = m2; n3 = m3;
        j += 4;
        have = nxt;
    }
    for (; j < e; j++) {
        uint2 v = __ldg(&gp[(size_t)__ldg(d_csr + j) * 32 + lane]);
        float2 f0 = __half22float2(*(__half2*)&v.x);
        float2 f1 = __half22float2(*(__half2*)&v.y);
        a0 += f0.x; a1 += f0.y; a2 += f1.x; a3 += f1.y;
    }

    float dv = d_dinv[node];
    float4 b = __ldg((const float4*)bias + lane);
    float4 r;
    r.x = fmaxf(fmaf(a0, dv, b.x), 0.f);
    r.y = fmaxf(fmaf(a1, dv, b.y), 0.f);
    r.z = fmaxf(fmaf(a2, dv, b.z), 0.f);
    r.w = fmaxf(fmaf(a3, dv, b.w), 0.f);
    ((float4*)out)[(size_t)node * 32 + lane] = r;
}

// layer 3: COLS=64 -> 32 half2/row; lane covers cols {2*lane, 2*lane+1}.
// Fused min-pool (bias deferred to k_final). Same index prefetching.
__global__ void k_agg64min(const __half* __restrict__ g, int N)
{
    __shared__ unsigned sMin[64];
    int tid = threadIdx.x;
    if (tid < 64) sMin[tid] = 0xFFFFFFFFu;
    __syncthreads();

    int node = (blockIdx.x * blockDim.x + tid) >> 5;
    int lane = tid & 31;
    if (node < N) {
        const unsigned* gp = (const unsigned*)g;
        float a0 = 0.f, a1 = 0.f;
        {
            unsigned v = __ldg(&gp[(size_t)node * 32 + lane]);
            float2 f = __half22float2(*(__half2*)&v);
            a0 += f.x; a1 += f.y;
        }
        int s = d_off[node], e = d_off[node + 1];
        int j = s;
        int n0, n1, n2, n3;
        bool have = (j + 4 <= e);
        if (have) {
            n0 = __ldg(d_csr + j);     n1 = __ldg(d_csr + j + 1);
            n2 = __ldg(d_csr + j + 2); n3 = __ldg(d_csr + j + 3);
        }
        while (have) {
            bool nxt = (j + 8 <= e);
            int m0, m1, m2, m3;
            if (nxt) {
                m0 = __ldg(d_csr + j + 4); m1 = __ldg(d_csr + j + 5);
                m2 = __ldg(d_csr + j + 6); m3 = __ldg(d_csr + j + 7);
            }
            unsigned v0 = __ldg(&gp[(size_t)n0 * 32 + lane]);
            unsigned v1 = __ldg(&gp[(size_t)n1 * 32 + lane]);
            unsigned v2 = __ldg(&gp[(size_t)n2 * 32 + lane]);
            unsigned v3 = __ldg(&gp[(size_t)n3 * 32 + lane]);
            float2 f;
            f = __half22float2(*(__half2*)&v0); a0 += f.x; a1 += f.y;
            f = __half22float2(*(__half2*)&v1); a0 += f.x; a1 += f.y;
            f = __half22float2(*(__half2*)&v2); a0 += f.x; a1 += f.y;
            f = __half22float2(*(__half2*)&v3); a0 += f.x; a1 += f.y;
            n0 = m0; n1 = m1; n2 = m2; n3 = m3;
            j += 4;
            have = nxt;
        }
        for (; j < e; j++) {
            unsigned v = __ldg(&gp[(size_t)__ldg(d_csr + j) * 32 + lane]);
            float2 f = __half22float2(*(__half2*)&v);
            a0 += f.x; a1 += f.y;
        }
        float dv = d_dinv[node];
        atomicMin(&sMin[2 * lane + 0], enc_f(a0 * dv));
        atomicMin(&sMin[2 * lane + 1], enc_f(a1 * dv));
    }
    __syncthreads();
    if (tid < 64) atomicMin(&d_gmin[tid], sMin[tid]);
}

__global__ void k_final(const float* __restrict__ b3, float* __restrict__ out) {
    int c = threadIdx.x;
    out[c] = dec_f(d_gmin[c]) + b3[c];
}

extern "C" void kernel_launch(void* const* d_in, const int* in_sizes, int n_in,
                              void* d_out, int out_size)
{
    const float* x  = (const float*)d_in[0];
    const int*   ei = (const int*)d_in[1];
    const float* W1 = (const float*)d_in[2];
    const float* b1 = (const float*)d_in[3];
    const float* W2 = (const float*)d_in[4];
    const float* b2 = (const float*)d_in[5];
    const float* W3 = (const float*)d_in[6];
    const float* b3 = (const float*)d_in[7];
    float* out = (float*)d_out;

    int N = in_sizes[0] / 128;
    int E = in_sizes[1] / 2;
    const int* src = ei;
    const int* dst = ei + E;

    float *B1, *B2;
    __half* G;
    cudaGetSymbolAddress((void**)&B1, d_B1);
    cudaGetSymbolAddress((void**)&B2, d_B2);
    cudaGetSymbolAddress((void**)&G, d_G);

    const int smem = (128 * (64 + 4) + 128 * 128) * 4;   // == (128*(128+4)+128*64)*4
    cudaFuncSetAttribute(k_gemm<128, 64, true>,  cudaFuncAttributeMaxDynamicSharedMemorySize, smem);
    cudaFuncSetAttribute(k_gemm<128, 64, false>, cudaFuncAttributeMaxDynamicSharedMemorySize, smem);
    cudaFuncSetAttribute(k_gemm<64, 128, false>, cudaFuncAttributeMaxDynamicSharedMemorySize, smem);

    // CSR: hist + scans (dinv ready after scan3; cnt/cur self-cleaned there)
    k_hist<<<(E + 255) / 256, 256>>>(dst, E);
    int nblk = (N + 1023) / 1024;
    k_scan1<<<nblk, 256>>>(N);
    k_scan2<<<1, 128>>>(nblk);
    k_scan3<<<(N + 255) / 256, 256>>>(N, E);

    // Layer-1 GEMM with CSR fill fused at LOW block ids (overlaps first waves)
    const int fillBlocks = 1024;
    int gb1 = (N + 63) / 64;
    k_gemm<128, 64, true><<<gb1 + fillBlocks, 128, smem>>>(x, W1, G, N, src, dst, E, fillBlocks);
    k_agg128<<<(N * 32 + 255) / 256, 256>>>(G, b1, B2, N);

    // Layer 2
    k_gemm<128, 64, false><<<(N + 63) / 64, 128, smem>>>(B2, W2, G, N, nullptr, nullptr, 0, 0);
    k_agg128<<<(N * 32 + 255) / 256, 256>>>(G, b2, B1, N);

    // Layer 3 (64 cols) + fused min-pool
    k_gemm<64, 128, false><<<(N + 127) / 128, 128, smem>>>(B1, W3, G, N, nullptr, nullptr, 0, 0);
    k_agg64min<<<(N * 32 + 255) / 256, 256>>>(G, N);

    k_final<<<1, 64>>>(b3, out);
}